// round 13
// baseline (speedup 1.0000x reference)
#include <cuda_runtime.h>

// Tensors [B=64, S=100, K=4, H=32, W=32] fp32; only channel k=3 is read:
// contiguous 1024-float run at s*4096 + 3072 for each of 6400 (b,s) slices.
// result = mean(|convdata[:,:,3] - output[:,:,3]|) over 6400*1024 elements.

static constexpr int NUM_SLICES   = 64 * 100;    // 6400
static constexpr int SLICE_STRIDE = 4 * 32 * 32; // 4096 floats per (b,s)
static constexpr int CH3_OFFSET   = 3 * 32 * 32; // 3072
static constexpr int SLICE_ELEMS  = 32 * 32;     // 1024 floats

static constexpr int THREADS = 256;              // one float4 per thread per slice
static constexpr int BLOCKS  = 320;              // single wave, even split
static constexpr int SLICES_PER_BLOCK = NUM_SLICES / BLOCKS;  // 20
static constexpr int CHUNK   = 4;                // slices per pipeline stage (8 LDG.128)
static constexpr int NCHUNKS = SLICES_PER_BLOCK / CHUNK;      // 5

// Cross-block fan-in scratch (device globals: allocation-free).
// Invariant: zero at every launch; last finishing block re-zeros after publishing.
__device__ float        g_accum = 0.0f;
__device__ unsigned int g_count = 0u;

__global__ __launch_bounds__(THREADS, 2) void abs_diff_mean_kernel(
    const float* __restrict__ a,   // "output" tensor
    const float* __restrict__ b,   // "convdata" tensor
    float* __restrict__ res)
{
    const int tid = threadIdx.x;

    // This block's 20 contiguous slices; thread t owns one float4 per slice.
    const size_t base = (size_t)blockIdx.x * SLICES_PER_BLOCK * SLICE_STRIDE
                      + CH3_OFFSET + (size_t)tid * 4;
    const float* pa = a + base;
    const float* pb = b + base;

    float4 ca[CHUNK], cb[CHUNK];   // current chunk (being consumed)
    float4 na[CHUNK], nb[CHUNK];   // next chunk (in flight)

    // Prologue: chunk 0 in flight (8 independent LDG.128).
    #pragma unroll
    for (int i = 0; i < CHUNK; i++) {
        ca[i] = *reinterpret_cast<const float4*>(pa + i * SLICE_STRIDE);
        cb[i] = *reinterpret_cast<const float4*>(pb + i * SLICE_STRIDE);
    }

    float acc0 = 0.0f, acc1 = 0.0f, acc2 = 0.0f, acc3 = 0.0f;

    // Steady state: prefetch chunk c while consuming chunk c-1 (16 loads in flight).
    #pragma unroll
    for (int c = 1; c < NCHUNKS; c++) {
        #pragma unroll
        for (int i = 0; i < CHUNK; i++) {
            const int s = c * CHUNK + i;
            na[i] = *reinterpret_cast<const float4*>(pa + s * SLICE_STRIDE);
            nb[i] = *reinterpret_cast<const float4*>(pb + s * SLICE_STRIDE);
        }
        #pragma unroll
        for (int i = 0; i < CHUNK; i++) {
            acc0 += fabsf(cb[i].x - ca[i].x);
            acc1 += fabsf(cb[i].y - ca[i].y);
            acc2 += fabsf(cb[i].z - ca[i].z);
            acc3 += fabsf(cb[i].w - ca[i].w);
            ca[i] = na[i];
            cb[i] = nb[i];
        }
    }

    // Epilogue: consume final chunk.
    #pragma unroll
    for (int i = 0; i < CHUNK; i++) {
        acc0 += fabsf(cb[i].x - ca[i].x);
        acc1 += fabsf(cb[i].y - ca[i].y);
        acc2 += fabsf(cb[i].z - ca[i].z);
        acc3 += fabsf(cb[i].w - ca[i].w);
    }

    float acc = (acc0 + acc1) + (acc2 + acc3);

    // Warp reduce
    #pragma unroll
    for (int off = 16; off > 0; off >>= 1)
        acc += __shfl_xor_sync(0xFFFFFFFFu, acc, off);

    __shared__ float warp_sums[THREADS / 32];
    if ((tid & 31) == 0) warp_sums[tid >> 5] = acc;
    __syncthreads();

    if (tid == 0) {
        float v = 0.0f;
        #pragma unroll
        for (int w = 0; w < THREADS / 32; w++) v += warp_sums[w];

        atomicAdd(&g_accum, v);
        __threadfence();
        unsigned int done = atomicAdd(&g_count, 1u);
        if (done == (unsigned)(gridDim.x - 1)) {
            float total = atomicExch(&g_accum, 0.0f);   // read + reset scratch
            const float inv_total = 1.0f / ((float)NUM_SLICES * (float)SLICE_ELEMS);
            res[0] = total * inv_total;
            g_count = 0u;                               // reset for next replay
        }
    }
}

extern "C" void kernel_launch(void* const* d_in, const int* in_sizes, int n_in,
                              void* d_out, int out_size) {
    const float* out_t  = (const float*)d_in[0];  // "output"
    const float* conv_t = (const float*)d_in[1];  // "convdata"
    float* res = (float*)d_out;

    abs_diff_mean_kernel<<<BLOCKS, THREADS>>>(out_t, conv_t, res);
}

// round 14
// speedup vs baseline: 1.2657x; 1.2657x over previous
#include <cuda_runtime.h>

// Tensors [B=64, S=100, K=4, H=32, W=32] fp32; only channel k=3 is read:
// contiguous 1024-float run at s*4096 + 3072 for each of 6400 (b,s) slices.
// result = mean(|convdata[:,:,3] - output[:,:,3]|) over 6400*1024 elements.

static constexpr int NUM_SLICES   = 64 * 100;    // 6400
static constexpr int SLICE_STRIDE = 4 * 32 * 32; // 4096 floats per (b,s)
static constexpr int CH3_OFFSET   = 3 * 32 * 32; // 3072
static constexpr int SLICE_ELEMS  = 32 * 32;     // 1024 floats

static constexpr int THREADS = 256;              // one float4 per thread per slice
static constexpr int BLOCKS  = 592;              // 148 SMs x 4 CTAs: exactly 4 resident CTAs/SM
static constexpr int FAT_BLOCKS = NUM_SLICES - BLOCKS * (NUM_SLICES / BLOCKS); // 480 blocks get 11
static constexpr int BASE_SLICES = NUM_SLICES / BLOCKS;                        // 10

// Cross-block fan-in scratch (device globals: allocation-free).
// Invariant: zero at every launch; last finishing block re-zeros after publishing.
__device__ float        g_accum = 0.0f;
__device__ unsigned int g_count = 0u;

__global__ __launch_bounds__(THREADS, 4) void abs_diff_mean_kernel(
    const float* __restrict__ a,   // "output" tensor
    const float* __restrict__ b,   // "convdata" tensor
    float* __restrict__ res)
{
    const int tid = threadIdx.x;
    const int bid = blockIdx.x;

    // Uneven contiguous partition: blocks [0,480) own 11 slices, the rest 10.
    const int extra = (bid < FAT_BLOCKS) ? bid : FAT_BLOCKS;
    const int start = bid * BASE_SLICES + extra;
    const int count = BASE_SLICES + ((bid < FAT_BLOCKS) ? 1 : 0);   // 10 or 11

    const size_t base = (size_t)start * SLICE_STRIDE + CH3_OFFSET + (size_t)tid * 4;
    const float* pa = a + base;
    const float* pb = b + base;

    const int npairs = count >> 1;   // 5
    const int tail   = count & 1;    // 0 or 1

    float4 ca0, ca1, cb0, cb1;       // current pair (being consumed)
    float4 na0, na1, nb0, nb1;       // next pair (in flight)

    // Prologue: pair 0 in flight (4 independent LDG.128).
    ca0 = *reinterpret_cast<const float4*>(pa);
    ca1 = *reinterpret_cast<const float4*>(pa + SLICE_STRIDE);
    cb0 = *reinterpret_cast<const float4*>(pb);
    cb1 = *reinterpret_cast<const float4*>(pb + SLICE_STRIDE);

    float acc0 = 0.0f, acc1 = 0.0f;

    // Steady state: prefetch pair c while consuming pair c-1 (8 loads in flight).
    for (int c = 1; c < npairs; c++) {
        const size_t s = (size_t)(2 * c) * SLICE_STRIDE;
        na0 = *reinterpret_cast<const float4*>(pa + s);
        na1 = *reinterpret_cast<const float4*>(pa + s + SLICE_STRIDE);
        nb0 = *reinterpret_cast<const float4*>(pb + s);
        nb1 = *reinterpret_cast<const float4*>(pb + s + SLICE_STRIDE);

        acc0 += fabsf(cb0.x - ca0.x) + fabsf(cb0.y - ca0.y);
        acc1 += fabsf(cb0.z - ca0.z) + fabsf(cb0.w - ca0.w);
        acc0 += fabsf(cb1.x - ca1.x) + fabsf(cb1.y - ca1.y);
        acc1 += fabsf(cb1.z - ca1.z) + fabsf(cb1.w - ca1.w);

        ca0 = na0; ca1 = na1; cb0 = nb0; cb1 = nb1;
    }

    // Tail slice prefetch (overlaps with last pair's consumption).
    if (tail) {
        const size_t s = (size_t)(2 * npairs) * SLICE_STRIDE;
        na0 = *reinterpret_cast<const float4*>(pa + s);
        nb0 = *reinterpret_cast<const float4*>(pb + s);
    }

    // Consume final pair.
    acc0 += fabsf(cb0.x - ca0.x) + fabsf(cb0.y - ca0.y);
    acc1 += fabsf(cb0.z - ca0.z) + fabsf(cb0.w - ca0.w);
    acc0 += fabsf(cb1.x - ca1.x) + fabsf(cb1.y - ca1.y);
    acc1 += fabsf(cb1.z - ca1.z) + fabsf(cb1.w - ca1.w);

    // Consume tail slice.
    if (tail) {
        acc0 += fabsf(nb0.x - na0.x) + fabsf(nb0.y - na0.y);
        acc1 += fabsf(nb0.z - na0.z) + fabsf(nb0.w - na0.w);
    }

    float acc = acc0 + acc1;

    // Warp reduce
    #pragma unroll
    for (int off = 16; off > 0; off >>= 1)
        acc += __shfl_xor_sync(0xFFFFFFFFu, acc, off);

    __shared__ float warp_sums[THREADS / 32];
    if ((tid & 31) == 0) warp_sums[tid >> 5] = acc;
    __syncthreads();

    if (tid == 0) {
        float v = 0.0f;
        #pragma unroll
        for (int w = 0; w < THREADS / 32; w++) v += warp_sums[w];

        atomicAdd(&g_accum, v);
        __threadfence();
        unsigned int done = atomicAdd(&g_count, 1u);
        if (done == (unsigned)(gridDim.x - 1)) {
            float total = atomicExch(&g_accum, 0.0f);   // read + reset scratch
            const float inv_total = 1.0f / ((float)NUM_SLICES * (float)SLICE_ELEMS);
            res[0] = total * inv_total;
            g_count = 0u;                               // reset for next replay
        }
    }
}

extern "C" void kernel_launch(void* const* d_in, const int* in_sizes, int n_in,
                              void* d_out, int out_size) {
    const float* out_t  = (const float*)d_in[0];  // "output"
    const float* conv_t = (const float*)d_in[1];  // "convdata"
    float* res = (float*)d_out;

    abs_diff_mean_kernel<<<BLOCKS, THREADS>>>(out_t, conv_t, res);
}